// round 13
// baseline (speedup 1.0000x reference)
#include <cuda_runtime.h>
#include <cuda_fp16.h>
#include <math.h>
#include <cstdint>

// Problem dims
#define BATCH 16384
#define FF    50
#define EE    64
#define FE    3200      // F*E
#define DD    512
#define NPAIR 1275      // F*(F+1)/2
#define KPAD  1280
#define HH1   1024
#define HH2   512

// mega-kernel block ranges
#define GRAM_BLOCKS 8192
#define PL_BLOCKS   1600
#define RK_BLOCKS   512
#define T0_BLOCKS   512
#define T1_BLOCKS   512
#define MEGA_BLOCKS (GRAM_BLOCKS + PL_BLOCKS + RK_BLOCKS + T0_BLOCKS + T1_BLOCKS)

// ---------------- scratch ----------------------------------------------------
__device__ __half g_emb [(size_t)BATCH * FE];
__device__ __half g_gram[(size_t)BATCH * KPAD];
__device__ __half g_PL  [(size_t)DD * FE];
__device__ __half g_R   [(size_t)DD * KPAD];
__device__ __half g_W0t [(size_t)HH1 * DD];
__device__ __half g_W1t [(size_t)HH2 * HH1];
__device__ __half g_y0h [(size_t)BATCH * DD];
__device__ __half g_y1h [(size_t)BATCH * HH1];
__device__ __half g_y2h [(size_t)BATCH * HH2];
__device__ float  g_pS  [128 * HH1];
__device__ float  g_pQ  [128 * HH1];
__device__ float  g_bnA1[HH1], g_bnB1[HH1];
__device__ float  g_bnA2[HH2], g_bnB2[HH2];
__device__ uint32_t g_pmap[KPAD];   // f1 | f2<<8 | (f1*72+f2)<<16

// ---------------- helpers -----------------------------------------------------
__device__ __forceinline__ uint32_t smem_u32(const void* p) {
    uint32_t a;
    asm("{ .reg .u64 t; cvta.to.shared.u64 t, %1; cvt.u32.u64 %0, t; }"
        : "=r"(a) : "l"(p));
    return a;
}

__device__ __forceinline__ void ldsm_x4(uint32_t r[4], uint32_t addr) {
    asm volatile("ldmatrix.sync.aligned.m8n8.x4.shared.b16 {%0,%1,%2,%3}, [%4];"
        : "=r"(r[0]), "=r"(r[1]), "=r"(r[2]), "=r"(r[3]) : "r"(addr));
}

__device__ __forceinline__ void mma16(float d[4], const uint32_t a[4], const uint32_t b[2]) {
    asm volatile(
        "mma.sync.aligned.m16n8k16.row.col.f32.f16.f16.f32 "
        "{%0,%1,%2,%3}, {%4,%5,%6,%7}, {%8,%9}, {%0,%1,%2,%3};"
        : "+f"(d[0]), "+f"(d[1]), "+f"(d[2]), "+f"(d[3])
        : "r"(a[0]), "r"(a[1]), "r"(a[2]), "r"(a[3]), "r"(b[0]), "r"(b[1]));
}

// BN+relu a packed half2 word with per-element coefficients
__device__ __forceinline__ uint32_t bnw(uint32_t w, float a0, float a1,
                                        float b0, float b1) {
    __half2 h = *reinterpret_cast<__half2*>(&w);
    float x = fmaxf(0.f, fmaf(__low2float(h),  a0, b0));
    float y = fmaxf(0.f, fmaf(__high2float(h), a1, b1));
    __half2 r = __floats2half2_rn(x, y);
    return *reinterpret_cast<uint32_t*>(&r);
}

#define CP16(dst, src) \
    asm volatile("cp.async.cg.shared.global [%0], [%1], 16;" :: "r"(dst), "l"(src))
#define CP_COMMIT() asm volatile("cp.async.commit_group;")
template<int N> __device__ __forceinline__ void cp_wait() {
    asm volatile("cp.async.wait_group %0;" :: "n"(N));
}

// generic swizzled tile: rows x 128B; (row, 16B-col 0..7)
__device__ __forceinline__ int swz_off(int r, int cc) {
    return r * 128 + 16 * (cc ^ (r & 7));
}
// packed BK=32 tile: 2 logical rows per 128B physical row
__device__ __forceinline__ int swz2(int m, int kc) {
    return (m >> 1) * 128 + 16 * ((((m & 1) * 4) + kc) ^ ((m >> 1) & 7));
}

// ---------------- K0: pmap ------------------------------------------------------
__global__ void pmap_kernel() {
    int p = blockIdx.x * 256 + threadIdx.x;
    if (p >= KPAD) return;
    int f1 = 0, rem = p;
    if (p < NPAIR) {
        while (rem >= FF - f1) { rem -= FF - f1; f1++; }
    } else { f1 = 0; rem = 0; }
    int f2 = f1 + rem;
    g_pmap[p] = (uint32_t)f1 | ((uint32_t)f2 << 8) | ((uint32_t)(f1 * 72 + f2) << 16);
}

// ---------------- MEGA: gram(+gather) | plcopy | rk | transposes ----------------
__global__ __launch_bounds__(256)
void mega_prep_kernel(const int* __restrict__ fidx,
                      const float* __restrict__ fval,
                      const float* __restrict__ femb,
                      const float* __restrict__ pl,
                      const float* __restrict__ q,
                      const float* __restrict__ W0,
                      const float* __restrict__ W1) {
    __shared__ __align__(16) char sm[2 * 8192 + 2 * 64 * 72 * 2];
    const int bid = blockIdx.x;
    const int tid = threadIdx.x;

    if (bid < GRAM_BLOCKS) {
        const int hb_id = tid >> 7;
        const int t = tid & 127;
        const int w4 = (tid >> 5) & 3;
        const int l = tid & 31;
        const size_t b = (size_t)bid * 2 + hb_id;

        char* E = sm + hb_id * 8192;
        __half* Cb = (__half*)(sm + 16384) + hb_id * 64 * 72;

        {
            int row = t >> 1, hb = t & 1;
            if (row < FF) {
                int i = fidx[b * FF + row];
                float v = fval[b * FF + row];
                const float4* src = (const float4*)(femb + (size_t)i * EE + hb * 32);
                __half* gout = g_emb + b * FE + (size_t)row * EE + hb * 32;
                #pragma unroll
                for (int j = 0; j < 4; j++) {
                    float4 f0 = src[j * 2], f1 = src[j * 2 + 1];
                    __half2 h[4];
                    h[0] = __floats2half2_rn(f0.x * v, f0.y * v);
                    h[1] = __floats2half2_rn(f0.z * v, f0.w * v);
                    h[2] = __floats2half2_rn(f1.x * v, f1.y * v);
                    h[3] = __floats2half2_rn(f1.z * v, f1.w * v);
                    uint4 u = *(uint4*)h;
                    *(uint4*)(E + swz_off(row, hb * 4 + j)) = u;
                    *(uint4*)(gout + j * 8) = u;
                }
            } else {
                #pragma unroll
                for (int j = 0; j < 4; j++)
                    *(uint4*)(E + swz_off(row, hb * 4 + j)) = make_uint4(0, 0, 0, 0);
            }
        }
        __syncthreads();

        const uint32_t Eb = smem_u32(E);
        const int mat = l >> 3, rowin = l & 7;

        uint32_t aoff[4];
        {
            int m = w4 * 16 + (mat & 1) * 8 + rowin;
            #pragma unroll
            for (int ks = 0; ks < 4; ks++)
                aoff[ks] = Eb + swz_off(m, ks * 2 + (mat >> 1));
        }
        uint32_t bfr[8][8];
        #pragma unroll
        for (int nj = 0; nj < 8; nj++) {
            int n = nj * 8 + rowin;
            #pragma unroll
            for (int kk = 0; kk < 2; kk++)
                ldsm_x4(&bfr[nj][kk * 4], Eb + swz_off(n, kk * 4 + mat));
        }

        float acc[8][4];
        #pragma unroll
        for (int nj = 0; nj < 8; nj++)
            #pragma unroll
            for (int qq = 0; qq < 4; qq++) acc[nj][qq] = 0.f;

        #pragma unroll
        for (int ks = 0; ks < 4; ks++) {
            uint32_t af[4];
            ldsm_x4(af, aoff[ks]);
            #pragma unroll
            for (int nj = 0; nj < 8; nj++)
                mma16(acc[nj], af, &bfr[nj][ks * 2]);
        }

        {
            int r = w4 * 16 + (l >> 2);
            int c = (l & 3) * 2;
            #pragma unroll
            for (int nj = 0; nj < 8; nj++) {
                int cc = c + nj * 8;
                Cb[r * 72 + cc]           = __float2half(acc[nj][0]);
                Cb[r * 72 + cc + 1]       = __float2half(acc[nj][1]);
                Cb[(r + 8) * 72 + cc]     = __float2half(acc[nj][2]);
                Cb[(r + 8) * 72 + cc + 1] = __float2half(acc[nj][3]);
            }
        }
        __syncthreads();

        __half* dst = g_gram + b * KPAD;
        #pragma unroll
        for (int it = 0; it < KPAD / 128; it++) {
            int p = t + it * 128;
            uint32_t m = g_pmap[p];
            __half v = (p < NPAIR) ? Cb[m >> 16] : __float2half(0.f);
            dst[p] = v;
        }
        return;
    }

    if (bid < GRAM_BLOCKS + PL_BLOCKS) {
        int pb = bid - GRAM_BLOCKS;
        size_t i = ((size_t)pb * 256 + tid) * 4;
        float4 f = *(const float4*)(pl + i);
        __half2 h0 = __floats2half2_rn(f.x, f.y);
        __half2 h1 = __floats2half2_rn(f.z, f.w);
        uint2 u = make_uint2(*(uint32_t*)&h0, *(uint32_t*)&h1);
        *(uint2*)(g_PL + i) = u;
        return;
    }

    if (bid < GRAM_BLOCKS + PL_BLOCKS + RK_BLOCKS) {
        int d = bid - GRAM_BLOCKS - PL_BLOCKS;
        const float* qd = q + d * FF;
        __half* dst = g_R + (size_t)d * KPAD;
        for (int p = tid; p < KPAD; p += 256) {
            uint32_t m = g_pmap[p];
            int f1 = m & 255, f2 = (m >> 8) & 255;
            float v = (p < NPAIR) ? qd[f1] * qd[f2] * ((f1 == f2) ? 1.f : 2.f) : 0.f;
            dst[p] = __float2half(v);
        }
        return;
    }

    float (*tile)[33] = (float(*)[33])sm;
    const int x = tid & 31, y = tid >> 5;
    const float* W; __half* Wt; int R, Cc, bx, by;
    if (bid < GRAM_BLOCKS + PL_BLOCKS + RK_BLOCKS + T0_BLOCKS) {
        int tb = bid - GRAM_BLOCKS - PL_BLOCKS - RK_BLOCKS;
        W = W0; Wt = g_W0t; R = DD; Cc = HH1;
        bx = tb & 31; by = tb >> 5;
    } else {
        int tb = bid - GRAM_BLOCKS - PL_BLOCKS - RK_BLOCKS - T0_BLOCKS;
        W = W1; Wt = g_W1t; R = HH1; Cc = HH2;
        bx = tb & 15; by = tb >> 4;
    }
    int c0 = bx * 32, r0 = by * 32;
    #pragma unroll
    for (int i = 0; i < 32; i += 8)
        tile[y + i][x] = W[(size_t)(r0 + y + i) * Cc + c0 + x];
    __syncthreads();
    #pragma unroll
    for (int i = 0; i < 32; i += 8)
        Wt[(size_t)(c0 + y + i) * R + r0 + x] = __float2half(tile[x][y + i]);
}

// ================= FUSED LZ + Y0 GEMM (proven config) ==========================
#define STAGE_BYTES 16384
#define STASH_OFF   (3 * STAGE_BYTES)
#define FUSED_SMEM  (3 * STAGE_BYTES + 128 * 132 * 2)

__global__ __launch_bounds__(128, 2)
void fused_gemm(const __half* __restrict__ A1, const __half* __restrict__ B1,
                const __half* __restrict__ A2, const __half* __restrict__ B2,
                __half* __restrict__ C, const float* __restrict__ pbias) {
    extern __shared__ char smem[];
    const uint32_t sb = smem_u32(smem);
    const int tid = threadIdx.x;
    const int l = tid & 31, w = tid >> 5;
    const int wm = w >> 1, wn = w & 1;
    const int m0 = blockIdx.y * 128, n0 = blockIdx.x * 128;
    const int NC1 = FE >> 5, NC2 = KPAD >> 5, NCT = NC1 + NC2;

    int aoffS[4], boffS[4];
    #pragma unroll
    for (int j = 0; j < 4; j++) {
        aoffS[j] = swz2(tid, j);
        boffS[j] = 8192 + swz2(tid, j);
    }
    const __half* Ap1 = A1 + (size_t)(m0 + tid) * FE;
    const __half* Bp1 = B1 + (size_t)(n0 + tid) * FE;
    const __half* Ap2 = A2 + (size_t)(m0 + tid) * KPAD;
    const __half* Bp2 = B2 + (size_t)(n0 + tid) * KPAD;

    const int mat = l >> 3, rowin = l & 7;
    uint32_t aoff[4][2], boff[8];
    #pragma unroll
    for (int mi = 0; mi < 4; mi++) {
        int m = wm * 64 + mi * 16 + (mat & 1) * 8 + rowin;
        #pragma unroll
        for (int ks = 0; ks < 2; ks++)
            aoff[mi][ks] = swz2(m, ks * 2 + (mat >> 1));
    }
    #pragma unroll
    for (int nj = 0; nj < 8; nj++) {
        int n = wn * 64 + nj * 8 + rowin;
        boff[nj] = 8192 + swz2(n, mat);
    }

    float acc[4][8][4];
    #pragma unroll
    for (int mi = 0; mi < 4; mi++)
        #pragma unroll
        for (int nj = 0; nj < 8; nj++)
            #pragma unroll
            for (int q = 0; q < 4; q++) acc[mi][nj][q] = 0.f;

    #define ISSUE(cc_, sidx_)                                                   \
        do {                                                                    \
            uint32_t base_ = sb + (sidx_) * STAGE_BYTES;                        \
            if ((cc_) < NC1) {                                                  \
                int kb_ = (cc_) * 32;                                           \
                _Pragma("unroll")                                               \
                for (int j = 0; j < 4; j++) CP16(base_ + aoffS[j], Ap1 + kb_ + j * 8); \
                _Pragma("unroll")                                               \
                for (int j = 0; j < 4; j++) CP16(base_ + boffS[j], Bp1 + kb_ + j * 8); \
            } else {                                                            \
                int kb_ = ((cc_) - NC1) * 32;                                   \
                _Pragma("unroll")                                               \
                for (int j = 0; j < 4; j++) CP16(base_ + aoffS[j], Ap2 + kb_ + j * 8); \
                _Pragma("unroll")                                               \
                for (int j = 0; j < 4; j++) CP16(base_ + boffS[j], Bp2 + kb_ + j * 8); \
            }                                                                   \
            CP_COMMIT();                                                        \
        } while (0)

    ISSUE(0, 0);
    ISSUE(1, 1);

    __half* stash = (__half*)(smem + STASH_OFF);
    const int rb = wm * 64 + (l >> 2);
    const int cb = wn * 64 + (l & 3) * 2;

    int buf = 0;
    for (int c = 0; c < NCT; c++) {
        if (c + 1 < NCT) cp_wait<1>(); else cp_wait<0>();
        __syncthreads();
        if (c + 2 < NCT) ISSUE(c + 2, (c + 2) % 3);

        if (c == NC1) {
            #pragma unroll
            for (int mi = 0; mi < 4; mi++) {
                int rr = rb + mi * 16;
                #pragma unroll
                for (int nj = 0; nj < 8; nj++) {
                    int cc = cb + nj * 8;
                    *(__half2*)(&stash[rr * 132 + cc]) =
                        __floats2half2_rn(acc[mi][nj][0], acc[mi][nj][1]);
                    *(__half2*)(&stash[(rr + 8) * 132 + cc]) =
                        __floats2half2_rn(acc[mi][nj][2], acc[mi][nj][3]);
                    acc[mi][nj][0] = 0.f; acc[mi][nj][1] = 0.f;
                    acc[mi][nj][2] = 0.f; acc[mi][nj][3] = 0.f;
                }
            }
        }

        const uint32_t S = sb + buf * STAGE_BYTES;
        uint32_t bfr[8][4];
        #pragma unroll
        for (int nj = 0; nj < 8; nj++) ldsm_x4(bfr[nj], S + boff[nj]);
        #pragma unroll
        for (int ks = 0; ks < 2; ks++) {
            uint32_t af[4][4];
            #pragma unroll
            for (int mi = 0; mi < 4; mi++) ldsm_x4(af[mi], S + aoff[mi][ks]);
            #pragma unroll
            for (int mi = 0; mi < 4; mi++)
                #pragma unroll
                for (int nj = 0; nj < 8; nj++)
                    mma16(acc[mi][nj], af[mi], &bfr[nj][ks * 2]);
        }
        buf = (buf + 1 == 3) ? 0 : buf + 1;
    }
    #undef ISSUE

    #pragma unroll
    for (int mi = 0; mi < 4; mi++) {
        int rr = rb + mi * 16;
        int r = m0 + rr;
        #pragma unroll
        for (int nj = 0; nj < 8; nj++) {
            int cc = cb + nj * 8;
            int cg = n0 + cc;
            __half2 lz0 = *(__half2*)(&stash[rr * 132 + cc]);
            __half2 lz1 = *(__half2*)(&stash[(rr + 8) * 132 + cc]);
            float pb0 = pbias[cg], pb1 = pbias[cg + 1];
            float d0 = fmaxf(0.f, __low2float(lz0)  + sqrtf(fmaxf(acc[mi][nj][0], 0.f)) + pb0);
            float d1 = fmaxf(0.f, __high2float(lz0) + sqrtf(fmaxf(acc[mi][nj][1], 0.f)) + pb1);
            float d2 = fmaxf(0.f, __low2float(lz1)  + sqrtf(fmaxf(acc[mi][nj][2], 0.f)) + pb0);
            float d3 = fmaxf(0.f, __high2float(lz1) + sqrtf(fmaxf(acc[mi][nj][3], 0.f)) + pb1);
            *(__half2*)(C + (size_t)r * DD + cg)       = __floats2half2_rn(d0, d1);
            *(__half2*)(C + (size_t)(r + 8) * DD + cg) = __floats2half2_rn(d2, d3);
        }
    }
}

// ---------------- fp16 HMMA GEMM: bias + BN partials; optional in-reg BN on A --
template<bool ABN>
__global__ __launch_bounds__(128, 2)
void hgemm(const __half* __restrict__ A, const __half* __restrict__ B,
           void* __restrict__ Cv, int Ntot, int K,
           const float* __restrict__ bias,
           const float* __restrict__ aA, const float* __restrict__ aB,
           float* __restrict__ statS, float* __restrict__ statQ) {
    extern __shared__ char smem[];
    const uint32_t sb = smem_u32(smem);
    const int tid = threadIdx.x;
    const int l = tid & 31, w = tid >> 5;
    const int wm = w >> 1, wn = w & 1;
    const int m0 = blockIdx.y * 128, n0 = blockIdx.x * 128;
    const int NC = K >> 5;

    int aoffS[4], boffS[4];
    #pragma unroll
    for (int j = 0; j < 4; j++) {
        aoffS[j] = swz2(tid, j);
        boffS[j] = 8192 + swz2(tid, j);
    }
    const __half* Ap = A + (size_t)(m0 + tid) * K;
    const __half* Bp = B + (size_t)(n0 + tid) * K;

    const int mat = l >> 3, rowin = l & 7;
    uint32_t aoff[4][2], boff[8];
    #pragma unroll
    for (int mi = 0; mi < 4; mi++) {
        int m = wm * 64 + mi * 16 + (mat & 1) * 8 + rowin;
        #pragma unroll
        for (int ks = 0; ks < 2; ks++)
            aoff[mi][ks] = swz2(m, ks * 2 + (mat >> 1));
    }
    #pragma unroll
    for (int nj = 0; nj < 8; nj++) {
        int n = wn * 64 + nj * 8 + rowin;
        boff[nj] = 8192 + swz2(n, mat);
    }

    float acc[4][8][4];
    #pragma unroll
    for (int mi = 0; mi < 4; mi++)
        #pragma unroll
        for (int nj = 0; nj < 8; nj++)
            #pragma unroll
            for (int q = 0; q < 4; q++) acc[mi][nj][q] = 0.f;

    #pragma unroll
    for (int s = 0; s < 2; s++) {
        uint32_t base = sb + s * STAGE_BYTES;
        int kb = s * 32;
        #pragma unroll
        for (int j = 0; j < 4; j++) CP16(base + aoffS[j], Ap + kb + j * 8);
        #pragma unroll
        for (int j = 0; j < 4; j++) CP16(base + boffS[j], Bp + kb + j * 8);
        CP_COMMIT();
    }

    int buf = 0;
    for (int c = 0; c < NC; c++) {
        if (c + 1 < NC) cp_wait<1>(); else cp_wait<0>();
        __syncthreads();
        if (c + 2 < NC) {
            int s = (c + 2) % 3;
            uint32_t base = sb + s * STAGE_BYTES;
            int kb = (c + 2) * 32;
            #pragma unroll
            for (int j = 0; j < 4; j++) CP16(base + aoffS[j], Ap + kb + j * 8);
            #pragma unroll
            for (int j = 0; j < 4; j++) CP16(base + boffS[j], Bp + kb + j * 8);
            CP_COMMIT();
        }
        const uint32_t S = sb + buf * STAGE_BYTES;
        uint32_t bfr[8][4];
        #pragma unroll
        for (int nj = 0; nj < 8; nj++) ldsm_x4(bfr[nj], S + boff[nj]);
        #pragma unroll
        for (int ks = 0; ks < 2; ks++) {
            uint32_t af[4][4];
            #pragma unroll
            for (int mi = 0; mi < 4; mi++) ldsm_x4(af[mi], S + aoff[mi][ks]);
            if (ABN) {
                // fragment k-columns: af[0],af[1] at kA..kA+1; af[2],af[3] at kA+8..kA+9
                int kA = c * 32 + ks * 16 + (l & 3) * 2;
                float a0 = aA[kA], a1 = aA[kA + 1], a2 = aA[kA + 8], a3 = aA[kA + 9];
                float b0 = aB[kA], b1 = aB[kA + 1], b2 = aB[kA + 8], b3 = aB[kA + 9];
                #pragma unroll
                for (int mi = 0; mi < 4; mi++) {
                    af[mi][0] = bnw(af[mi][0], a0, a1, b0, b1);
                    af[mi][1] = bnw(af[mi][1], a0, a1, b0, b1);
                    af[mi][2] = bnw(af[mi][2], a2, a3, b2, b3);
                    af[mi][3] = bnw(af[mi][3], a2, a3, b2, b3);
                }
            }
            #pragma unroll
            for (int mi = 0; mi < 4; mi++)
                #pragma unroll
                for (int nj = 0; nj < 8; nj++)
                    mma16(acc[mi][nj], af[mi], &bfr[nj][ks * 2]);
        }
        buf = (buf + 1 == 3) ? 0 : buf + 1;
    }

    __half* Ch = (__half*)Cv;
    const int r0 = m0 + wm * 64 + (l >> 2);
    const int c0b = n0 + wn * 64 + (l & 3) * 2;
    float sS[8][2] = {}, sQ[8][2] = {};
    #pragma unroll
    for (int mi = 0; mi < 4; mi++) {
        int r = r0 + mi * 16;
        #pragma unroll
        for (int nj = 0; nj < 8; nj++) {
            int cc = c0b + nj * 8;
            float d0 = acc[mi][nj][0], d1 = acc[mi][nj][1];
            float d2 = acc[mi][nj][2], d3 = acc[mi][nj][3];
            float b0v = bias[cc], b1v = bias[cc + 1];
            d0 += b0v; d1 += b1v; d2 += b0v; d3 += b1v;
            sS[nj][0] += d0 + d2;           sS[nj][1] += d1 + d3;
            sQ[nj][0] += d0 * d0 + d2 * d2; sQ[nj][1] += d1 * d1 + d3 * d3;
            *(__half2*)(Ch + (size_t)r * Ntot + cc)       = __floats2half2_rn(d0, d1);
            *(__half2*)(Ch + (size_t)(r + 8) * Ntot + cc) = __floats2half2_rn(d2, d3);
        }
    }
    #pragma unroll
    for (int nj = 0; nj < 8; nj++)
        #pragma unroll
        for (int e = 0; e < 2; e++) {
            #pragma unroll
            for (int off = 4; off < 32; off <<= 1) {
                sS[nj][e] += __shfl_xor_sync(0xffffffffu, sS[nj][e], off);
                sQ[nj][e] += __shfl_xor_sync(0xffffffffu, sQ[nj][e], off);
            }
        }
    float* sf = (float*)smem;
    __syncthreads();
    if (l < 4) {
        #pragma unroll
        for (int nj = 0; nj < 8; nj++)
            #pragma unroll
            for (int e = 0; e < 2; e++) {
                int cl = wn * 64 + nj * 8 + (l & 3) * 2 + e;
                sf[wm * 128 + cl]       = sS[nj][e];
                sf[256 + wm * 128 + cl] = sQ[nj][e];
            }
    }
    __syncthreads();
    if (tid < 128) {
        statS[(size_t)blockIdx.y * Ntot + n0 + tid] = sf[tid] + sf[128 + tid];
        statQ[(size_t)blockIdx.y * Ntot + n0 + tid] = sf[256 + tid] + sf[384 + tid];
    }
}

// ---------------- BN finalize ----------------------------------------------
__global__ void bnfin_kernel(const float* __restrict__ pS,
                             const float* __restrict__ pQ, int H,
                             const float* __restrict__ scale,
                             const float* __restrict__ offset,
                             float* __restrict__ oA, float* __restrict__ oB) {
    int c = blockIdx.x * blockDim.x + threadIdx.x;
    if (c >= H) return;
    float s = 0.f, q = 0.f;
    for (int t = 0; t < 128; t++) { s += pS[t * H + c]; q += pQ[t * H + c]; }
    float m = s * (1.f / (float)BATCH);
    float v = q * (1.f / (float)BATCH) - m * m;
    float a = scale[0] * rsqrtf(fmaxf(v, 0.f) + 1e-10f);
    oA[c] = a;
    oB[c] = offset[0] - m * a;
}

// ---------------- output head: warp per row, 8 rows/block --------------------
__global__ void out_kernel(const float* __restrict__ w,
                           const float* __restrict__ ob,
                           float* __restrict__ out) {
    int wid = threadIdx.x >> 5, l = threadIdx.x & 31;
    int b = blockIdx.x * 8 + wid;
    const __half* row = g_y2h + (size_t)b * HH2;
    float s = 0.f;
    #pragma unroll
    for (int k = 0; k < HH2 / 32; k++) {
        int n = l + k * 32;
        float v = fmaxf(0.f, fmaf(__half2float(row[n]), g_bnA2[n], g_bnB2[n]));
        s += v * w[n];
    }
    #pragma unroll
    for (int off = 16; off > 0; off >>= 1)
        s += __shfl_xor_sync(0xffffffffu, s, off);
    if (l == 0) {
        float x = s + ob[0];
        out[b] = 1.f / (1.f + expf(-x));
    }
}

// ---------------- launch ----------------------------------------------------
extern "C" void kernel_launch(void* const* d_in, const int* in_sizes, int n_in,
                              void* d_out, int out_size) {
    const int*   fidx  = (const int*)  d_in[0];
    const float* fval  = (const float*)d_in[1];
    const float* femb  = (const float*)d_in[2];
    const float* pl    = (const float*)d_in[3];
    const float* pbias = (const float*)d_in[4];
    const float* pq    = (const float*)d_in[5];
    const float* W0    = (const float*)d_in[6];
    const float* b0    = (const float*)d_in[7];
    const float* W1    = (const float*)d_in[8];
    const float* b1    = (const float*)d_in[9];
    const float* bnS   = (const float*)d_in[10];
    const float* bnO   = (const float*)d_in[11];
    const float* ow    = (const float*)d_in[12];
    const float* ob    = (const float*)d_in[13];
    float* out = (float*)d_out;

    void *emb, *gram, *PL, *R, *W0t, *W1t, *y0h, *y1h, *y2h, *pS, *pQ;
    void *A1, *B1, *A2, *B2;
    cudaGetSymbolAddress(&emb,  g_emb);
    cudaGetSymbolAddress(&gram, g_gram);
    cudaGetSymbolAddress(&PL,   g_PL);
    cudaGetSymbolAddress(&R,    g_R);
    cudaGetSymbolAddress(&W0t,  g_W0t);
    cudaGetSymbolAddress(&W1t,  g_W1t);
    cudaGetSymbolAddress(&y0h,  g_y0h);
    cudaGetSymbolAddress(&y1h,  g_y1h);
    cudaGetSymbolAddress(&y2h,  g_y2h);
    cudaGetSymbolAddress(&pS,   g_pS);
    cudaGetSymbolAddress(&pQ,   g_pQ);
    cudaGetSymbolAddress(&A1,   g_bnA1);
    cudaGetSymbolAddress(&B1,   g_bnB1);
    cudaGetSymbolAddress(&A2,   g_bnA2);
    cudaGetSymbolAddress(&B2,   g_bnB2);

    const int SMEM = 3 * STAGE_BYTES;   // 48 KB
    cudaFuncSetAttribute(fused_gemm, cudaFuncAttributeMaxDynamicSharedMemorySize, FUSED_SMEM);
    cudaFuncSetAttribute(hgemm<false>, cudaFuncAttributeMaxDynamicSharedMemorySize, SMEM);
    cudaFuncSetAttribute(hgemm<true>,  cudaFuncAttributeMaxDynamicSharedMemorySize, SMEM);

    pmap_kernel<<<(KPAD + 255) / 256, 256>>>();                                  // 0
    mega_prep_kernel<<<MEGA_BLOCKS, 256>>>(fidx, fval, femb, pl, pq, W0, W1);    // 1
    // 2: fused LZ + y0
    fused_gemm<<<dim3(4, 128), 128, FUSED_SMEM>>>(
        (const __half*)emb, (const __half*)PL,
        (const __half*)gram, (const __half*)R,
        (__half*)y0h, pbias);
    // 3: y1 = y0 @ W0 + b0, with BN partials  <-- profiled launch
    hgemm<false><<<dim3(8, 128), 128, SMEM>>>(
        (const __half*)y0h, (const __half*)W0t, y1h, HH1, DD,
        b0, nullptr, nullptr, (float*)pS, (float*)pQ);
    bnfin_kernel<<<HH1 / 256, 256>>>((const float*)pS, (const float*)pQ, HH1,
                                     bnS, bnO, (float*)A1, (float*)B1);
    // y2 = bnrelu(y1) @ W1 + b1, BN applied in-register on A fragments
    hgemm<true><<<dim3(4, 128), 128, SMEM>>>(
        (const __half*)y1h, (const __half*)W1t, y2h, HH2, HH1,
        b1, (const float*)A1, (const float*)B1, (float*)pS, (float*)pQ);
    bnfin_kernel<<<HH2 / 256, 256>>>((const float*)pS, (const float*)pQ, HH2,
                                     bnS, bnO, (float*)A2, (float*)B2);
    out_kernel<<<BATCH / 8, 256>>>(ow, ob, out);
}

// round 14
// speedup vs baseline: 1.0115x; 1.0115x over previous
#include <cuda_runtime.h>
#include <cuda_fp16.h>
#include <math.h>
#include <cstdint>

// Problem dims
#define BATCH 16384
#define FF    50
#define EE    64
#define FE    3200      // F*E
#define DD    512
#define NPAIR 1275      // F*(F+1)/2
#define KPAD  1280
#define HH1   1024
#define HH2   512

// mega-kernel block ranges
#define GRAM_BLOCKS 8192
#define PL_BLOCKS   1600
#define RK_BLOCKS   512
#define T0_BLOCKS   512
#define T1_BLOCKS   512
#define MEGA_BLOCKS (GRAM_BLOCKS + PL_BLOCKS + RK_BLOCKS + T0_BLOCKS + T1_BLOCKS)

// ---------------- scratch ----------------------------------------------------
__device__ __half g_emb [(size_t)BATCH * FE];
__device__ __half g_gram[(size_t)BATCH * KPAD];
__device__ __half g_PL  [(size_t)DD * FE];
__device__ __half g_R   [(size_t)DD * KPAD];
__device__ __half g_W0t [(size_t)HH1 * DD];
__device__ __half g_W1t [(size_t)HH2 * HH1];
__device__ __half g_y0h [(size_t)BATCH * DD];
__device__ __half g_y1h [(size_t)BATCH * HH1];
__device__ __half g_y2h [(size_t)BATCH * HH2];
__device__ float  g_pS  [128 * HH1];
__device__ float  g_pQ  [128 * HH1];
__device__ float  g_bnA2[HH2], g_bnB2[HH2];
__device__ __half g_bnA1h[HH1], g_bnB1h[HH1];   // packed half coeffs for hgemm2 ABN
__device__ uint32_t g_pmap[KPAD];   // f1 | f2<<8 | (f1*72+f2)<<16

// ---------------- helpers -----------------------------------------------------
__device__ __forceinline__ uint32_t smem_u32(const void* p) {
    uint32_t a;
    asm("{ .reg .u64 t; cvta.to.shared.u64 t, %1; cvt.u32.u64 %0, t; }"
        : "=r"(a) : "l"(p));
    return a;
}

__device__ __forceinline__ void ldsm_x4(uint32_t r[4], uint32_t addr) {
    asm volatile("ldmatrix.sync.aligned.m8n8.x4.shared.b16 {%0,%1,%2,%3}, [%4];"
        : "=r"(r[0]), "=r"(r[1]), "=r"(r[2]), "=r"(r[3]) : "r"(addr));
}

__device__ __forceinline__ void mma16(float d[4], const uint32_t a[4], const uint32_t b[2]) {
    asm volatile(
        "mma.sync.aligned.m16n8k16.row.col.f32.f16.f16.f32 "
        "{%0,%1,%2,%3}, {%4,%5,%6,%7}, {%8,%9}, {%0,%1,%2,%3};"
        : "+f"(d[0]), "+f"(d[1]), "+f"(d[2]), "+f"(d[3])
        : "r"(a[0]), "r"(a[1]), "r"(a[2]), "r"(a[3]), "r"(b[0]), "r"(b[1]));
}

// BN+relu packed half2 with packed half2 coefficients (native h2 math)
__device__ __forceinline__ uint32_t bnw2(uint32_t w, uint32_t a, uint32_t b) {
    __half2 h = *reinterpret_cast<__half2*>(&w);
    __half2 r = __hfma2(h, *reinterpret_cast<__half2*>(&a),
                           *reinterpret_cast<__half2*>(&b));
    r = __hmax2(r, __half2half2(__float2half(0.f)));
    return *reinterpret_cast<uint32_t*>(&r);
}

#define CP16(dst, src) \
    asm volatile("cp.async.cg.shared.global [%0], [%1], 16;" :: "r"(dst), "l"(src))
#define CP_COMMIT() asm volatile("cp.async.commit_group;")
template<int N> __device__ __forceinline__ void cp_wait() {
    asm volatile("cp.async.wait_group %0;" :: "n"(N));
}

// generic swizzled tile: rows x 128B; (row, 16B-col 0..7)
__device__ __forceinline__ int swz_off(int r, int cc) {
    return r * 128 + 16 * (cc ^ (r & 7));
}
// packed BK=32 tile: 2 logical rows per 128B physical row
__device__ __forceinline__ int swz2(int m, int kc) {
    return (m >> 1) * 128 + 16 * ((((m & 1) * 4) + kc) ^ ((m >> 1) & 7));
}

// ---------------- K0: pmap ------------------------------------------------------
__global__ void pmap_kernel() {
    int p = blockIdx.x * 256 + threadIdx.x;
    if (p >= KPAD) return;
    int f1 = 0, rem = p;
    if (p < NPAIR) {
        while (rem >= FF - f1) { rem -= FF - f1; f1++; }
    } else { f1 = 0; rem = 0; }
    int f2 = f1 + rem;
    g_pmap[p] = (uint32_t)f1 | ((uint32_t)f2 << 8) | ((uint32_t)(f1 * 72 + f2) << 16);
}

// ---------------- MEGA: gram(+gather) | plcopy | rk | transposes ----------------
__global__ __launch_bounds__(256)
void mega_prep_kernel(const int* __restrict__ fidx,
                      const float* __restrict__ fval,
                      const float* __restrict__ femb,
                      const float* __restrict__ pl,
                      const float* __restrict__ q,
                      const float* __restrict__ W0,
                      const float* __restrict__ W1) {
    __shared__ __align__(16) char sm[2 * 8192 + 2 * 64 * 72 * 2];
    const int bid = blockIdx.x;
    const int tid = threadIdx.x;

    if (bid < GRAM_BLOCKS) {
        const int hb_id = tid >> 7;
        const int t = tid & 127;
        const int w4 = (tid >> 5) & 3;
        const int l = tid & 31;
        const size_t b = (size_t)bid * 2 + hb_id;

        char* E = sm + hb_id * 8192;
        __half* Cb = (__half*)(sm + 16384) + hb_id * 64 * 72;

        {
            int row = t >> 1, hb = t & 1;
            if (row < FF) {
                int i = fidx[b * FF + row];
                float v = fval[b * FF + row];
                const float4* src = (const float4*)(femb + (size_t)i * EE + hb * 32);
                __half* gout = g_emb + b * FE + (size_t)row * EE + hb * 32;
                #pragma unroll
                for (int j = 0; j < 4; j++) {
                    float4 f0 = src[j * 2], f1 = src[j * 2 + 1];
                    __half2 h[4];
                    h[0] = __floats2half2_rn(f0.x * v, f0.y * v);
                    h[1] = __floats2half2_rn(f0.z * v, f0.w * v);
                    h[2] = __floats2half2_rn(f1.x * v, f1.y * v);
                    h[3] = __floats2half2_rn(f1.z * v, f1.w * v);
                    uint4 u = *(uint4*)h;
                    *(uint4*)(E + swz_off(row, hb * 4 + j)) = u;
                    *(uint4*)(gout + j * 8) = u;
                }
            } else {
                #pragma unroll
                for (int j = 0; j < 4; j++)
                    *(uint4*)(E + swz_off(row, hb * 4 + j)) = make_uint4(0, 0, 0, 0);
            }
        }
        __syncthreads();

        const uint32_t Eb = smem_u32(E);
        const int mat = l >> 3, rowin = l & 7;

        uint32_t aoff[4];
        {
            int m = w4 * 16 + (mat & 1) * 8 + rowin;
            #pragma unroll
            for (int ks = 0; ks < 4; ks++)
                aoff[ks] = Eb + swz_off(m, ks * 2 + (mat >> 1));
        }
        uint32_t bfr[8][8];
        #pragma unroll
        for (int nj = 0; nj < 8; nj++) {
            int n = nj * 8 + rowin;
            #pragma unroll
            for (int kk = 0; kk < 2; kk++)
                ldsm_x4(&bfr[nj][kk * 4], Eb + swz_off(n, kk * 4 + mat));
        }

        float acc[8][4];
        #pragma unroll
        for (int nj = 0; nj < 8; nj++)
            #pragma unroll
            for (int qq = 0; qq < 4; qq++) acc[nj][qq] = 0.f;

        #pragma unroll
        for (int ks = 0; ks < 4; ks++) {
            uint32_t af[4];
            ldsm_x4(af, aoff[ks]);
            #pragma unroll
            for (int nj = 0; nj < 8; nj++)
                mma16(acc[nj], af, &bfr[nj][ks * 2]);
        }

        {
            int r = w4 * 16 + (l >> 2);
            int c = (l & 3) * 2;
            #pragma unroll
            for (int nj = 0; nj < 8; nj++) {
                int cc = c + nj * 8;
                Cb[r * 72 + cc]           = __float2half(acc[nj][0]);
                Cb[r * 72 + cc + 1]       = __float2half(acc[nj][1]);
                Cb[(r + 8) * 72 + cc]     = __float2half(acc[nj][2]);
                Cb[(r + 8) * 72 + cc + 1] = __float2half(acc[nj][3]);
            }
        }
        __syncthreads();

        __half* dst = g_gram + b * KPAD;
        #pragma unroll
        for (int it = 0; it < KPAD / 128; it++) {
            int p = t + it * 128;
            uint32_t m = g_pmap[p];
            __half v = (p < NPAIR) ? Cb[m >> 16] : __float2half(0.f);
            dst[p] = v;
        }
        return;
    }

    if (bid < GRAM_BLOCKS + PL_BLOCKS) {
        int pb = bid - GRAM_BLOCKS;
        size_t i = ((size_t)pb * 256 + tid) * 4;
        float4 f = *(const float4*)(pl + i);
        __half2 h0 = __floats2half2_rn(f.x, f.y);
        __half2 h1 = __floats2half2_rn(f.z, f.w);
        uint2 u = make_uint2(*(uint32_t*)&h0, *(uint32_t*)&h1);
        *(uint2*)(g_PL + i) = u;
        return;
    }

    if (bid < GRAM_BLOCKS + PL_BLOCKS + RK_BLOCKS) {
        int d = bid - GRAM_BLOCKS - PL_BLOCKS;
        const float* qd = q + d * FF;
        __half* dst = g_R + (size_t)d * KPAD;
        for (int p = tid; p < KPAD; p += 256) {
            uint32_t m = g_pmap[p];
            int f1 = m & 255, f2 = (m >> 8) & 255;
            float v = (p < NPAIR) ? qd[f1] * qd[f2] * ((f1 == f2) ? 1.f : 2.f) : 0.f;
            dst[p] = __float2half(v);
        }
        return;
    }

    float (*tile)[33] = (float(*)[33])sm;
    const int x = tid & 31, y = tid >> 5;
    const float* W; __half* Wt; int R, Cc, bx, by;
    if (bid < GRAM_BLOCKS + PL_BLOCKS + RK_BLOCKS + T0_BLOCKS) {
        int tb = bid - GRAM_BLOCKS - PL_BLOCKS - RK_BLOCKS;
        W = W0; Wt = g_W0t; R = DD; Cc = HH1;
        bx = tb & 31; by = tb >> 5;
    } else {
        int tb = bid - GRAM_BLOCKS - PL_BLOCKS - RK_BLOCKS - T0_BLOCKS;
        W = W1; Wt = g_W1t; R = HH1; Cc = HH2;
        bx = tb & 15; by = tb >> 4;
    }
    int c0 = bx * 32, r0 = by * 32;
    #pragma unroll
    for (int i = 0; i < 32; i += 8)
        tile[y + i][x] = W[(size_t)(r0 + y + i) * Cc + c0 + x];
    __syncthreads();
    #pragma unroll
    for (int i = 0; i < 32; i += 8)
        Wt[(size_t)(c0 + y + i) * R + r0 + x] = __float2half(tile[x][y + i]);
}

// ================= FUSED LZ + Y0 GEMM (proven config) ==========================
#define STAGE_BYTES 16384
#define STASH_OFF   (3 * STAGE_BYTES)
#define FUSED_SMEM  (3 * STAGE_BYTES + 128 * 132 * 2)

__global__ __launch_bounds__(128, 2)
void fused_gemm(const __half* __restrict__ A1, const __half* __restrict__ B1,
                const __half* __restrict__ A2, const __half* __restrict__ B2,
                __half* __restrict__ C, const float* __restrict__ pbias) {
    extern __shared__ char smem[];
    const uint32_t sb = smem_u32(smem);
    const int tid = threadIdx.x;
    const int l = tid & 31, w = tid >> 5;
    const int wm = w >> 1, wn = w & 1;
    const int m0 = blockIdx.y * 128, n0 = blockIdx.x * 128;
    const int NC1 = FE >> 5, NC2 = KPAD >> 5, NCT = NC1 + NC2;

    int aoffS[4], boffS[4];
    #pragma unroll
    for (int j = 0; j < 4; j++) {
        aoffS[j] = swz2(tid, j);
        boffS[j] = 8192 + swz2(tid, j);
    }
    const __half* Ap1 = A1 + (size_t)(m0 + tid) * FE;
    const __half* Bp1 = B1 + (size_t)(n0 + tid) * FE;
    const __half* Ap2 = A2 + (size_t)(m0 + tid) * KPAD;
    const __half* Bp2 = B2 + (size_t)(n0 + tid) * KPAD;

    const int mat = l >> 3, rowin = l & 7;
    uint32_t aoff[4][2], boff[8];
    #pragma unroll
    for (int mi = 0; mi < 4; mi++) {
        int m = wm * 64 + mi * 16 + (mat & 1) * 8 + rowin;
        #pragma unroll
        for (int ks = 0; ks < 2; ks++)
            aoff[mi][ks] = swz2(m, ks * 2 + (mat >> 1));
    }
    #pragma unroll
    for (int nj = 0; nj < 8; nj++) {
        int n = wn * 64 + nj * 8 + rowin;
        boff[nj] = 8192 + swz2(n, mat);
    }

    float acc[4][8][4];
    #pragma unroll
    for (int mi = 0; mi < 4; mi++)
        #pragma unroll
        for (int nj = 0; nj < 8; nj++)
            #pragma unroll
            for (int q = 0; q < 4; q++) acc[mi][nj][q] = 0.f;

    #define ISSUE(cc_, sidx_)                                                   \
        do {                                                                    \
            uint32_t base_ = sb + (sidx_) * STAGE_BYTES;                        \
            if ((cc_) < NC1) {                                                  \
                int kb_ = (cc_) * 32;                                           \
                _Pragma("unroll")                                               \
                for (int j = 0; j < 4; j++) CP16(base_ + aoffS[j], Ap1 + kb_ + j * 8); \
                _Pragma("unroll")                                               \
                for (int j = 0; j < 4; j++) CP16(base_ + boffS[j], Bp1 + kb_ + j * 8); \
            } else {                                                            \
                int kb_ = ((cc_) - NC1) * 32;                                   \
                _Pragma("unroll")                                               \
                for (int j = 0; j < 4; j++) CP16(base_ + aoffS[j], Ap2 + kb_ + j * 8); \
                _Pragma("unroll")                                               \
                for (int j = 0; j < 4; j++) CP16(base_ + boffS[j], Bp2 + kb_ + j * 8); \
            }                                                                   \
            CP_COMMIT();                                                        \
        } while (0)

    ISSUE(0, 0);
    ISSUE(1, 1);

    __half* stash = (__half*)(smem + STASH_OFF);
    const int rb = wm * 64 + (l >> 2);
    const int cb = wn * 64 + (l & 3) * 2;

    int buf = 0;
    for (int c = 0; c < NCT; c++) {
        if (c + 1 < NCT) cp_wait<1>(); else cp_wait<0>();
        __syncthreads();
        if (c + 2 < NCT) ISSUE(c + 2, (c + 2) % 3);

        if (c == NC1) {
            #pragma unroll
            for (int mi = 0; mi < 4; mi++) {
                int rr = rb + mi * 16;
                #pragma unroll
                for (int nj = 0; nj < 8; nj++) {
                    int cc = cb + nj * 8;
                    *(__half2*)(&stash[rr * 132 + cc]) =
                        __floats2half2_rn(acc[mi][nj][0], acc[mi][nj][1]);
                    *(__half2*)(&stash[(rr + 8) * 132 + cc]) =
                        __floats2half2_rn(acc[mi][nj][2], acc[mi][nj][3]);
                    acc[mi][nj][0] = 0.f; acc[mi][nj][1] = 0.f;
                    acc[mi][nj][2] = 0.f; acc[mi][nj][3] = 0.f;
                }
            }
        }

        const uint32_t S = sb + buf * STAGE_BYTES;
        uint32_t bfr[8][4];
        #pragma unroll
        for (int nj = 0; nj < 8; nj++) ldsm_x4(bfr[nj], S + boff[nj]);
        #pragma unroll
        for (int ks = 0; ks < 2; ks++) {
            uint32_t af[4][4];
            #pragma unroll
            for (int mi = 0; mi < 4; mi++) ldsm_x4(af[mi], S + aoff[mi][ks]);
            #pragma unroll
            for (int mi = 0; mi < 4; mi++)
                #pragma unroll
                for (int nj = 0; nj < 8; nj++)
                    mma16(acc[mi][nj], af[mi], &bfr[nj][ks * 2]);
        }
        buf = (buf + 1 == 3) ? 0 : buf + 1;
    }
    #undef ISSUE

    #pragma unroll
    for (int mi = 0; mi < 4; mi++) {
        int rr = rb + mi * 16;
        int r = m0 + rr;
        #pragma unroll
        for (int nj = 0; nj < 8; nj++) {
            int cc = cb + nj * 8;
            int cg = n0 + cc;
            __half2 lz0 = *(__half2*)(&stash[rr * 132 + cc]);
            __half2 lz1 = *(__half2*)(&stash[(rr + 8) * 132 + cc]);
            float pb0 = pbias[cg], pb1 = pbias[cg + 1];
            float d0 = fmaxf(0.f, __low2float(lz0)  + sqrtf(fmaxf(acc[mi][nj][0], 0.f)) + pb0);
            float d1 = fmaxf(0.f, __high2float(lz0) + sqrtf(fmaxf(acc[mi][nj][1], 0.f)) + pb1);
            float d2 = fmaxf(0.f, __low2float(lz1)  + sqrtf(fmaxf(acc[mi][nj][2], 0.f)) + pb0);
            float d3 = fmaxf(0.f, __high2float(lz1) + sqrtf(fmaxf(acc[mi][nj][3], 0.f)) + pb1);
            *(__half2*)(C + (size_t)r * DD + cg)       = __floats2half2_rn(d0, d1);
            *(__half2*)(C + (size_t)(r + 8) * DD + cg) = __floats2half2_rn(d2, d3);
        }
    }
}

// ---------------- fp16 HMMA GEMM: bias + BN partials; optional h2 BN on A ------
template<bool ABN>
__global__ __launch_bounds__(128, 2)
void hgemm(const __half* __restrict__ A, const __half* __restrict__ B,
           void* __restrict__ Cv, int Ntot, int K,
           const float* __restrict__ bias,
           const __half* __restrict__ aAh, const __half* __restrict__ aBh,
           float* __restrict__ statS, float* __restrict__ statQ) {
    extern __shared__ char smem[];
    const uint32_t sb = smem_u32(smem);
    const int tid = threadIdx.x;
    const int l = tid & 31, w = tid >> 5;
    const int wm = w >> 1, wn = w & 1;
    const int m0 = blockIdx.y * 128, n0 = blockIdx.x * 128;
    const int NC = K >> 5;

    int aoffS[4], boffS[4];
    #pragma unroll
    for (int j = 0; j < 4; j++) {
        aoffS[j] = swz2(tid, j);
        boffS[j] = 8192 + swz2(tid, j);
    }
    const __half* Ap = A + (size_t)(m0 + tid) * K;
    const __half* Bp = B + (size_t)(n0 + tid) * K;

    const int mat = l >> 3, rowin = l & 7;
    uint32_t aoff[4][2], boff[8];
    #pragma unroll
    for (int mi = 0; mi < 4; mi++) {
        int m = wm * 64 + mi * 16 + (mat & 1) * 8 + rowin;
        #pragma unroll
        for (int ks = 0; ks < 2; ks++)
            aoff[mi][ks] = swz2(m, ks * 2 + (mat >> 1));
    }
    #pragma unroll
    for (int nj = 0; nj < 8; nj++) {
        int n = wn * 64 + nj * 8 + rowin;
        boff[nj] = 8192 + swz2(n, mat);
    }

    float acc[4][8][4];
    #pragma unroll
    for (int mi = 0; mi < 4; mi++)
        #pragma unroll
        for (int nj = 0; nj < 8; nj++)
            #pragma unroll
            for (int q = 0; q < 4; q++) acc[mi][nj][q] = 0.f;

    #pragma unroll
    for (int s = 0; s < 2; s++) {
        uint32_t base = sb + s * STAGE_BYTES;
        int kb = s * 32;
        #pragma unroll
        for (int j = 0; j < 4; j++) CP16(base + aoffS[j], Ap + kb + j * 8);
        #pragma unroll
        for (int j = 0; j < 4; j++) CP16(base + boffS[j], Bp + kb + j * 8);
        CP_COMMIT();
    }

    int buf = 0;
    for (int c = 0; c < NC; c++) {
        if (c + 1 < NC) cp_wait<1>(); else cp_wait<0>();
        __syncthreads();
        if (c + 2 < NC) {
            int s = (c + 2) % 3;
            uint32_t base = sb + s * STAGE_BYTES;
            int kb = (c + 2) * 32;
            #pragma unroll
            for (int j = 0; j < 4; j++) CP16(base + aoffS[j], Ap + kb + j * 8);
            #pragma unroll
            for (int j = 0; j < 4; j++) CP16(base + boffS[j], Bp + kb + j * 8);
            CP_COMMIT();
        }
        const uint32_t S = sb + buf * STAGE_BYTES;
        uint32_t bfr[8][4];
        #pragma unroll
        for (int nj = 0; nj < 8; nj++) ldsm_x4(bfr[nj], S + boff[nj]);
        #pragma unroll
        for (int ks = 0; ks < 2; ks++) {
            uint32_t af[4][4];
            #pragma unroll
            for (int mi = 0; mi < 4; mi++) ldsm_x4(af[mi], S + aoff[mi][ks]);
            if (ABN) {
                // af[0],af[1] hold k-cols kA,kA+1; af[2],af[3] hold kA+8,kA+9
                int kA = c * 32 + ks * 16 + (l & 3) * 2;
                uint32_t a01 = *(const uint32_t*)(aAh + kA);
                uint32_t b01 = *(const uint32_t*)(aBh + kA);
                uint32_t a89 = *(const uint32_t*)(aAh + kA + 8);
                uint32_t b89 = *(const uint32_t*)(aBh + kA + 8);
                #pragma unroll
                for (int mi = 0; mi < 4; mi++) {
                    af[mi][0] = bnw2(af[mi][0], a01, b01);
                    af[mi][1] = bnw2(af[mi][1], a01, b01);
                    af[mi][2] = bnw2(af[mi][2], a89, b89);
                    af[mi][3] = bnw2(af[mi][3], a89, b89);
                }
            }
            #pragma unroll
            for (int mi = 0; mi < 4; mi++)
                #pragma unroll
                for (int nj = 0; nj < 8; nj++)
                    mma16(acc[mi][nj], af[mi], &bfr[nj][ks * 2]);
        }
        buf = (buf + 1 == 3) ? 0 : buf + 1;
    }

    __half* Ch = (__half*)Cv;
    const int r0 = m0 + wm * 64 + (l >> 2);
    const int c0b = n0 + wn * 64 + (l & 3) * 2;
    float sS[8][2] = {}, sQ[8][2] = {};
    #pragma unroll
    for (int mi = 0; mi < 4; mi++) {
        int r = r0 + mi * 16;
        #pragma unroll
        for (int nj = 0; nj < 8; nj++) {
            int cc = c0b + nj * 8;
            float d0 = acc[mi][nj][0], d1 = acc[mi][nj][1];
            float d2 = acc[mi][nj][2], d3 = acc[mi][nj][3];
            float b0v = bias[cc], b1v = bias[cc + 1];
            d0 += b0v; d1 += b1v; d2 += b0v; d3 += b1v;
            sS[nj][0] += d0 + d2;           sS[nj][1] += d1 + d3;
            sQ[nj][0] += d0 * d0 + d2 * d2; sQ[nj][1] += d1 * d1 + d3 * d3;
            *(__half2*)(Ch + (size_t)r * Ntot + cc)       = __floats2half2_rn(d0, d1);
            *(__half2*)(Ch + (size_t)(r + 8) * Ntot + cc) = __floats2half2_rn(d2, d3);
        }
    }
    #pragma unroll
    for (int nj = 0; nj < 8; nj++)
        #pragma unroll
        for (int e = 0; e < 2; e++) {
            #pragma unroll
            for (int off = 4; off < 32; off <<= 1) {
                sS[nj][e] += __shfl_xor_sync(0xffffffffu, sS[nj][e], off);
                sQ[nj][e] += __shfl_xor_sync(0xffffffffu, sQ[nj][e], off);
            }
        }
    float* sf = (float*)smem;
    __syncthreads();
    if (l < 4) {
        #pragma unroll
        for (int nj = 0; nj < 8; nj++)
            #pragma unroll
            for (int e = 0; e < 2; e++) {
                int cl = wn * 64 + nj * 8 + (l & 3) * 2 + e;
                sf[wm * 128 + cl]       = sS[nj][e];
                sf[256 + wm * 128 + cl] = sQ[nj][e];
            }
    }
    __syncthreads();
    if (tid < 128) {
        statS[(size_t)blockIdx.y * Ntot + n0 + tid] = sf[tid] + sf[128 + tid];
        statQ[(size_t)blockIdx.y * Ntot + n0 + tid] = sf[256 + tid] + sf[384 + tid];
    }
}

// ---------------- BN finalize: float coeffs + optional packed half coeffs ------
__global__ void bnfin_kernel(const float* __restrict__ pS,
                             const float* __restrict__ pQ, int H,
                             const float* __restrict__ scale,
                             const float* __restrict__ offset,
                             float* __restrict__ oA, float* __restrict__ oB,
                             __half* __restrict__ oAh, __half* __restrict__ oBh) {
    int c = blockIdx.x * blockDim.x + threadIdx.x;
    if (c >= H) return;
    float s = 0.f, q = 0.f;
    for (int t = 0; t < 128; t++) { s += pS[t * H + c]; q += pQ[t * H + c]; }
    float m = s * (1.f / (float)BATCH);
    float v = q * (1.f / (float)BATCH) - m * m;
    float a = scale[0] * rsqrtf(fmaxf(v, 0.f) + 1e-10f);
    float b = offset[0] - m * a;
    if (oA)  { oA[c] = a; oB[c] = b; }
    if (oAh) { oAh[c] = __float2half(a); oBh[c] = __float2half(b); }
}

// ---------------- output head: warp per row, 8 rows/block --------------------
__global__ void out_kernel(const float* __restrict__ w,
                           const float* __restrict__ ob,
                           float* __restrict__ out) {
    int wid = threadIdx.x >> 5, l = threadIdx.x & 31;
    int b = blockIdx.x * 8 + wid;
    const __half* row = g_y2h + (size_t)b * HH2;
    float s = 0.f;
    #pragma unroll
    for (int k = 0; k < HH2 / 32; k++) {
        int n = l + k * 32;
        float v = fmaxf(0.f, fmaf(__half2float(row[n]), g_bnA2[n], g_bnB2[n]));
        s += v * w[n];
    }
    #pragma unroll
    for (int off = 16; off > 0; off >>= 1)
        s += __shfl_xor_sync(0xffffffffu, s, off);
    if (l == 0) {
        float x = s + ob[0];
        out[b] = 1.f / (1.f + expf(-x));
    }
}

// ---------------- launch ----------------------------------------------------
extern "C" void kernel_launch(void* const* d_in, const int* in_sizes, int n_in,
                              void* d_out, int out_size) {
    const int*   fidx  = (const int*)  d_in[0];
    const float* fval  = (const float*)d_in[1];
    const float* femb  = (const float*)d_in[2];
    const float* pl    = (const float*)d_in[3];
    const float* pbias = (const float*)d_in[4];
    const float* pq    = (const float*)d_in[5];
    const float* W0    = (const float*)d_in[6];
    const float* b0    = (const float*)d_in[7];
    const float* W1    = (const float*)d_in[8];
    const float* b1    = (const float*)d_in[9];
    const float* bnS   = (const float*)d_in[10];
    const float* bnO   = (const float*)d_in[11];
    const float* ow    = (const float*)d_in[12];
    const float* ob    = (const float*)d_in[13];
    float* out = (float*)d_out;

    void *emb, *gram, *PL, *R, *W0t, *W1t, *y0h, *y1h, *y2h, *pS, *pQ;
    void *A1h, *B1h, *A2, *B2;
    cudaGetSymbolAddress(&emb,  g_emb);
    cudaGetSymbolAddress(&gram, g_gram);
    cudaGetSymbolAddress(&PL,   g_PL);
    cudaGetSymbolAddress(&R,    g_R);
    cudaGetSymbolAddress(&W0t,  g_W0t);
    cudaGetSymbolAddress(&W1t,  g_W1t);
    cudaGetSymbolAddress(&y0h,  g_y0h);
    cudaGetSymbolAddress(&y1h,  g_y1h);
    cudaGetSymbolAddress(&y2h,  g_y2h);
    cudaGetSymbolAddress(&pS,   g_pS);
    cudaGetSymbolAddress(&pQ,   g_pQ);
    cudaGetSymbolAddress(&A1h,  g_bnA1h);
    cudaGetSymbolAddress(&B1h,  g_bnB1h);
    cudaGetSymbolAddress(&A2,   g_bnA2);
    cudaGetSymbolAddress(&B2,   g_bnB2);

    const int SMEM = 3 * STAGE_BYTES;   // 48 KB
    cudaFuncSetAttribute(fused_gemm, cudaFuncAttributeMaxDynamicSharedMemorySize, FUSED_SMEM);
    cudaFuncSetAttribute(hgemm<false>, cudaFuncAttributeMaxDynamicSharedMemorySize, SMEM);
    cudaFuncSetAttribute(hgemm<true>,  cudaFuncAttributeMaxDynamicSharedMemorySize, SMEM);

    pmap_kernel<<<(KPAD + 255) / 256, 256>>>();                                  // 0
    mega_prep_kernel<<<MEGA_BLOCKS, 256>>>(fidx, fval, femb, pl, pq, W0, W1);    // 1
    // 2: fused LZ + y0
    fused_gemm<<<dim3(4, 128), 128, FUSED_SMEM>>>(
        (const __half*)emb, (const __half*)PL,
        (const __half*)gram, (const __half*)R,
        (__half*)y0h, pbias);
    // 3: y1 = y0 @ W0 + b0, with BN partials  <-- profiled launch
    hgemm<false><<<dim3(8, 128), 128, SMEM>>>(
        (const __half*)y0h, (const __half*)W0t, y1h, HH1, DD,
        b0, nullptr, nullptr, (float*)pS, (float*)pQ);
    bnfin_kernel<<<HH1 / 256, 256>>>((const float*)pS, (const float*)pQ, HH1,
                                     bnS, bnO, nullptr, nullptr,
                                     (__half*)A1h, (__half*)B1h);
    // y2 = bnrelu(y1) @ W1 + b1; BN applied on A fragments in native half2
    hgemm<true><<<dim3(4, 128), 128, SMEM>>>(
        (const __half*)y1h, (const __half*)W1t, y2h, HH2, HH1,
        b1, (const __half*)A1h, (const __half*)B1h, (float*)pS, (float*)pQ);
    bnfin_kernel<<<HH2 / 256, 256>>>((const float*)pS, (const float*)pQ, HH2,
                                     bnS, bnO, (float*)A2, (float*)B2,
                                     nullptr, nullptr);
    out_kernel<<<BATCH / 8, 256>>>(ow, ob, out);
}